// round 13
// baseline (speedup 1.0000x reference)
#include <cuda_runtime.h>
#include <cuda_bf16.h>
#include <cstdint>
#include <cstddef>

// Problem dims
#define B_   16
#define S_   1024
#define D_   768
#define H_   384
#define G4   1536          // 4*H
#define M_   16384         // B*S
#define K2   2304          // split-GEMM K'' = 3*768

// ---------------- scratch (static device allocations, 256B aligned) ----------------
__device__ __align__(256) float g_xprojF[(size_t)M_ * G4];
__device__ __align__(256) float g_xprojB[(size_t)M_ * G4];
__device__ __align__(256) float g_lstm  [(size_t)M_ * 768];
__device__ __align__(256) float g_hcat  [(size_t)M_ * 768];
__device__ __align__(256) float g_h2    [(size_t)M_ * H_];
__device__ __align__(256) float g_mlp1  [(size_t)M_ * 256];
__device__ __align__(256) float g_mlp2  [(size_t)M_ * 96];
__device__ __align__(256) __nv_bfloat16 g_A2[(size_t)M_ * K2];   // split A
__device__ __align__(256) __nv_bfloat16 g_W2[(size_t)G4 * K2];   // split W
// dataflow step-counters: 256 producers (2 dir x 4 bg x 32 ug), 32B stride
__device__ __align__(256) unsigned g_cnt[256 * 8];

// ---------------- packed f32x2 helpers ----------------
__device__ __forceinline__ void fma2_(unsigned long long& d,
                                      unsigned long long a,
                                      unsigned long long b) {
    asm("fma.rn.f32x2 %0, %1, %2, %0;" : "+l"(d) : "l"(a), "l"(b));
}
__device__ __forceinline__ unsigned long long pack2_(float x, float y) {
    unsigned long long d;
    asm("mov.b64 %0, {%1, %2};" : "=l"(d) : "f"(x), "f"(y));
    return d;
}
__device__ __forceinline__ float2 unpack2_(unsigned long long v) {
    float2 r;
    asm("mov.b64 {%0, %1}, %2;" : "=f"(r.x), "=f"(r.y) : "l"(v));
    return r;
}

// ---------------- generic SIMT GEMM (MLP head) ----------------
template<int ACT>
__global__ __launch_bounds__(256, 2) void gemm_bias_kernel(
    const float* __restrict__ A, const float* __restrict__ W,
    const float* __restrict__ bias, float* __restrict__ C,
    int M, int N, int K, int ldc)
{
    __shared__ float sA[16][132];
    __shared__ float sB[16][132];
    int tid = threadIdx.x;
    int m0 = blockIdx.y * 128;
    int n0 = blockIdx.x * 128;
    int tx = tid & 15, ty = tid >> 4;

    unsigned long long acc2[8][4];
#pragma unroll
    for (int i = 0; i < 8; i++)
#pragma unroll
        for (int j = 0; j < 4; j++) acc2[i][j] = 0ULL;

    for (int k0 = 0; k0 < K; k0 += 16) {
#pragma unroll
        for (int e = 0; e < 2; e++) {
            int f4 = tid + 256 * e;
            int r  = f4 >> 2;
            int c4 = (f4 & 3) << 2;
            float4 av = *(const float4*)(A + (size_t)(m0 + r) * K + k0 + c4);
            sA[c4 + 0][r] = av.x; sA[c4 + 1][r] = av.y;
            sA[c4 + 2][r] = av.z; sA[c4 + 3][r] = av.w;
            int n = n0 + r;
            float4 wv = make_float4(0.f, 0.f, 0.f, 0.f);
            if (n < N) wv = *(const float4*)(W + (size_t)n * K + k0 + c4);
            sB[c4 + 0][r] = wv.x; sB[c4 + 1][r] = wv.y;
            sB[c4 + 2][r] = wv.z; sB[c4 + 3][r] = wv.w;
        }
        __syncthreads();
#pragma unroll
        for (int kk = 0; kk < 16; kk++) {
            float a[8];
            *(float4*)&a[0] = *(const float4*)&sA[kk][ty * 8];
            *(float4*)&a[4] = *(const float4*)&sA[kk][ty * 8 + 4];
            ulonglong2 bv0 = *(const ulonglong2*)&sB[kk][tx * 8];
            ulonglong2 bv1 = *(const ulonglong2*)&sB[kk][tx * 8 + 4];
            unsigned long long b2[4] = {bv0.x, bv0.y, bv1.x, bv1.y};
#pragma unroll
            for (int i = 0; i < 8; i++) {
                unsigned long long a2 = pack2_(a[i], a[i]);
#pragma unroll
                for (int j = 0; j < 4; j++)
                    fma2_(acc2[i][j], a2, b2[j]);
            }
        }
        __syncthreads();
    }

#pragma unroll
    for (int i = 0; i < 8; i++) {
        int m = m0 + ty * 8 + i;
#pragma unroll
        for (int j2 = 0; j2 < 4; j2++) {
            float2 p = unpack2_(acc2[i][j2]);
            int n = n0 + tx * 8 + j2 * 2;
            if (n < N) {
                float v0 = p.x + bias[n];
                if (ACT) v0 = fmaxf(v0, 0.f);
                C[(size_t)m * ldc + n] = v0;
            }
            if (n + 1 < N) {
                float v1 = p.y + bias[n + 1];
                if (ACT) v1 = fmaxf(v1, 0.f);
                C[(size_t)m * ldc + n + 1] = v1;
            }
        }
    }
}

// ---------------- bf16 split prep ----------------
// mode 0 (A): [hi | hi | lo]     mode 1 (W): [hi | lo | hi]
__global__ __launch_bounds__(256) void split_prep_kernel(
    const float* __restrict__ in, __nv_bfloat16* __restrict__ out,
    int nquads, int mode)
{
    int g = blockIdx.x * blockDim.x + threadIdx.x;
    if (g >= nquads) return;
    int m = g / 192;
    int q = (g % 192) * 4;
    float4 v = *(const float4*)(in + (size_t)m * 768 + q);
    float a[4] = {v.x, v.y, v.z, v.w};
    float h0 = __bfloat162float(__float2bfloat16(a[0]));
    float h1 = __bfloat162float(__float2bfloat16(a[1]));
    float h2 = __bfloat162float(__float2bfloat16(a[2]));
    float h3 = __bfloat162float(__float2bfloat16(a[3]));
    __nv_bfloat162 hi01 = __nv_bfloat162(__float2bfloat16(a[0]), __float2bfloat16(a[1]));
    __nv_bfloat162 hi23 = __nv_bfloat162(__float2bfloat16(a[2]), __float2bfloat16(a[3]));
    __nv_bfloat162 lo01 = __nv_bfloat162(__float2bfloat16(a[0] - h0), __float2bfloat16(a[1] - h1));
    __nv_bfloat162 lo23 = __nv_bfloat162(__float2bfloat16(a[2] - h2), __float2bfloat16(a[3] - h3));
    __nv_bfloat16* o = out + (size_t)m * K2 + q;
    *(__nv_bfloat162*)(o + 0) = hi01;  *(__nv_bfloat162*)(o + 2) = hi23;
    if (mode == 0) {
        *(__nv_bfloat162*)(o + 768)  = hi01;  *(__nv_bfloat162*)(o + 770)  = hi23;
        *(__nv_bfloat162*)(o + 1536) = lo01;  *(__nv_bfloat162*)(o + 1538) = lo23;
    } else {
        *(__nv_bfloat162*)(o + 768)  = lo01;  *(__nv_bfloat162*)(o + 770)  = lo23;
        *(__nv_bfloat162*)(o + 1536) = hi01;  *(__nv_bfloat162*)(o + 1538) = hi23;
    }
}

// ---------------- warp-MMA bf16 GEMM: C[M,N] = A2 @ W2^T + bias ----------------
#define TG_NBLK 36          // K2 / 64

__device__ __forceinline__ uint32_t smem_u32_(const void* p) {
    uint32_t a;
    asm("{ .reg .u64 t; cvta.to.shared.u64 t, %1; cvt.u32.u64 %0, t; }" : "=r"(a) : "l"(p));
    return a;
}
__device__ __forceinline__ uint32_t swz_(uint32_t off) {
    return off ^ ((off >> 3) & 0x70);
}
__device__ __forceinline__ void cp16_(uint32_t s, const void* g) {
    asm volatile("cp.async.cg.shared.global [%0], [%1], 16;" :: "r"(s), "l"(g) : "memory");
}
#define LDSM4_(d0, d1, d2, d3, addr) \
    asm volatile("ldmatrix.sync.aligned.m8n8.x4.shared.b16 {%0,%1,%2,%3}, [%4];" \
                 : "=r"(d0), "=r"(d1), "=r"(d2), "=r"(d3) : "r"(addr))
#define MMA16816_(c, a, b0, b1) \
    asm volatile("mma.sync.aligned.m16n8k16.row.col.f32.bf16.bf16.f32 " \
                 "{%0,%1,%2,%3}, {%4,%5,%6,%7}, {%8,%9}, {%0,%1,%2,%3};" \
                 : "+f"((c)[0]), "+f"((c)[1]), "+f"((c)[2]), "+f"((c)[3]) \
                 : "r"((a)[0]), "r"((a)[1]), "r"((a)[2]), "r"((a)[3]), \
                   "r"(b0), "r"(b1))

__global__ __launch_bounds__(256) void tgemm_kernel(
    const __nv_bfloat16* __restrict__ A2,
    const __nv_bfloat16* __restrict__ W2,
    const float* __restrict__ bias,
    float* __restrict__ C, int ldc)
{
    extern __shared__ char smraw[];
    uint32_t sb = smem_u32_(smraw);
    int tid  = threadIdx.x;
    int wid  = tid >> 5;
    int lane = tid & 31;
    int n0 = blockIdx.x * 128;
    int m0 = blockIdx.y * 128;
    int wm = (wid & 3) * 32;
    int wn = (wid >> 2) * 64;

    float acc[2][8][4];
#pragma unroll
    for (int mt = 0; mt < 2; mt++)
#pragma unroll
        for (int nt = 0; nt < 8; nt++)
#pragma unroll
            for (int e = 0; e < 4; e++) acc[mt][nt][e] = 0.f;

    int arow = wm + (lane & 15);
    uint32_t arowoff = (uint32_t)arow * 128;
    uint32_t amask   = (uint32_t)(arow & 7) << 4;
    uint32_t akh     = (uint32_t)(lane >> 4) * 16;

    int brow = wn + (lane & 7) + ((lane >> 4) << 3);
    uint32_t browoff = (uint32_t)brow * 128;
    uint32_t bmask   = (uint32_t)(brow & 7) << 4;
    uint32_t bkh     = (uint32_t)((lane >> 3) & 1) * 16;

#pragma unroll
    for (int i = 0; i < 4; i++) {
        int cid = tid + 256 * i;
        int row = cid >> 3, ch = cid & 7;
        uint32_t so = swz_((uint32_t)row * 128 + (uint32_t)ch * 16);
        cp16_(sb + so,           A2 + (size_t)(m0 + row) * K2 + ch * 8);
        cp16_(sb + 32768 + so,   W2 + (size_t)(n0 + row) * K2 + ch * 8);
    }
    asm volatile("cp.async.commit_group;" ::: "memory");

    for (int blk = 0; blk < TG_NBLK; blk++) {
        int bufc = blk & 1;
        if (blk + 1 < TG_NBLK) {
            int bufn = (blk + 1) & 1;
            size_t gk = (size_t)(blk + 1) * 64;
#pragma unroll
            for (int i = 0; i < 4; i++) {
                int cid = tid + 256 * i;
                int row = cid >> 3, ch = cid & 7;
                uint32_t so = swz_((uint32_t)row * 128 + (uint32_t)ch * 16);
                cp16_(sb + bufn * 16384 + so,
                      A2 + (size_t)(m0 + row) * K2 + gk + ch * 8);
                cp16_(sb + 32768 + bufn * 16384 + so,
                      W2 + (size_t)(n0 + row) * K2 + gk + ch * 8);
            }
            asm volatile("cp.async.commit_group;" ::: "memory");
            asm volatile("cp.async.wait_group 1;" ::: "memory");
        } else {
            asm volatile("cp.async.wait_group 0;" ::: "memory");
        }
        __syncthreads();

        uint32_t abuf = sb + bufc * 16384;
        uint32_t bbuf = sb + 32768 + bufc * 16384;
#pragma unroll
        for (int kk = 0; kk < 4; kk++) {
            uint32_t acol = (akh + (uint32_t)kk * 32) ^ amask;
            uint32_t bcol = (bkh + (uint32_t)kk * 32) ^ bmask;
            uint32_t a[2][4], b[4][4];
#pragma unroll
            for (int mt = 0; mt < 2; mt++)
                LDSM4_(a[mt][0], a[mt][1], a[mt][2], a[mt][3],
                       abuf + arowoff + mt * 2048 + acol);
#pragma unroll
            for (int g = 0; g < 4; g++)
                LDSM4_(b[g][0], b[g][1], b[g][2], b[g][3],
                       bbuf + browoff + g * 2048 + bcol);
#pragma unroll
            for (int mt = 0; mt < 2; mt++)
#pragma unroll
                for (int nt = 0; nt < 8; nt++) {
                    int g = nt >> 1, h = (nt & 1) * 2;
                    MMA16816_(acc[mt][nt], a[mt], b[g][h], b[g][h + 1]);
                }
        }
        __syncthreads();
    }

#pragma unroll
    for (int mt = 0; mt < 2; mt++)
#pragma unroll
        for (int nt = 0; nt < 8; nt++) {
            int row = m0 + wm + mt * 16 + (lane >> 2);
            int col = n0 + wn + nt * 8 + (lane & 3) * 2;
            float2 bv = *(const float2*)(bias + col);
            float2 o0 = make_float2(acc[mt][nt][0] + bv.x, acc[mt][nt][1] + bv.y);
            float2 o1 = make_float2(acc[mt][nt][2] + bv.x, acc[mt][nt][3] + bv.y);
            *(float2*)(C + (size_t)row * ldc + col) = o0;
            *(float2*)(C + (size_t)(row + 8) * ldc + col) = o1;
        }
}

// ---------------- LSTM scan: both directions per CTA, pipelined phases ----------------
// 128 CTAs = 4 batch-groups (NBX=4) x 32 unit-groups (NUX=12). Each CTA runs F then
// B phases per step; both dirs' Whh in registers; ONE __syncthreads per step-pair.
// B flags are ~a phase old when polled -> detect is ~pure L2 visibility. s_p is
// double-buffered per dir so warps 3-7 run a full phase ahead of combine.
#define NUX   12
#define NBX   4
#define HSTR  392
#define PBUFD (NBX * 48 * 32)    // 6144 floats per dir per buffer
#define NCTA  128
#define TPB   256

__device__ __forceinline__ float sigm_(float x) { return 1.f / (1.f + __expf(-x)); }
__device__ __forceinline__ float tanh_(float x) {
    float t = __expf(-2.f * fabsf(x));
    float r = (1.f - t) / (1.f + t);
    return x < 0.f ? -r : r;
}
__device__ __forceinline__ void red_release_add(unsigned* p) {
    asm volatile("red.release.gpu.global.add.u32 [%0], %1;" :: "l"(p), "r"(1u) : "memory");
}
__device__ __forceinline__ unsigned ld_relaxed(const unsigned* p) {
    unsigned v;
    asm volatile("ld.relaxed.gpu.global.u32 %0, [%1];" : "=r"(v) : "l"(p) : "memory");
    return v;
}

__global__ void flags_zero_kernel()
{
    g_cnt[threadIdx.x * 8] = 0u;
}

__global__ __launch_bounds__(TPB, 1) void lstm_scan_kernel(
    const float* __restrict__ xpF, const float* __restrict__ xpB,
    const float* __restrict__ WhhF, const float* __restrict__ WhhB,
    float* __restrict__ out /* [B,S,768]: fwd cols 0:384, bwd 384:768 */)
{
    extern __shared__ float sm[];
    float* s_h = sm;                         // 2 * NBX * HSTR   (3136 fl)
    float* s_p = s_h + 2 * NBX * HSTR;       // 4 * PBUFD        (24576 fl)
    float* s_c = s_p + 4 * PBUFD;            // 2 * 48

    int tid  = threadIdx.x;
    int wrp  = tid >> 5;
    int lane = tid & 31;
    int bg  = blockIdx.x >> 5;     // 0..3
    int ug  = blockIdx.x & 31;
    int u0  = ug * NUX;
    int bb0 = bg * NBX;

    int ql    = lane & 3;
    int rt    = lane >> 2;
    int kbase = wrp * 48 + ql * 12;
    int r0    = rt * 6;
    int qg    = wrp * 4 + ql;

    // Whh slices for BOTH dirs in registers (row-pairs packed for f32x2)
    unsigned long long w2[2][3][12];
#pragma unroll
    for (int d = 0; d < 2; d++) {
        const float* Whh = d ? WhhB : WhhF;
#pragma unroll
        for (int rp = 0; rp < 3; rp++) {
            int ra = r0 + 2 * rp, rb = ra + 1;
            const float* Wa = Whh + (size_t)((ra / NUX) * H_ + u0 + (ra % NUX)) * H_ + kbase;
            const float* Wb = Whh + (size_t)((rb / NUX) * H_ + u0 + (rb % NUX)) * H_ + kbase;
#pragma unroll
            for (int k = 0; k < 12; k++)
                w2[d][rp][k] = pack2_(__ldg(Wa + k), __ldg(Wb + k));
        }
    }
    if (tid < 96) s_c[tid] = 0.f;

    // zero s_h both dirs
    for (int idx = tid; idx < 2 * NBX * (H_ / 4); idx += TPB) {
        int d  = idx / (NBX * 96);
        int rr = idx % (NBX * 96);
        int b  = rr / 96;
        int c4 = (rr % 96) * 4;
        *(float4*)&s_h[(d * NBX + b) * HSTR + c4] = make_float4(0.f, 0.f, 0.f, 0.f);
    }
    __syncthreads();

    int cw = tid % 48;                  // combine role within dir (tid < 96)
    int cd = tid / 48;                  // combine dir (0=F, 1=B)
    int cb = cw / NUX, cu = cw % NUX;
    unsigned* mycnt = &g_cnt[((cd * 4 + bg) * 32 + ug) * 8];
    int buf = 0;

    for (int step = 0; step < S_; step++) {
        int ttF = step, ttB = S_ - 1 - step;

        // prefetch xproj for this step's gate combine (both dirs, tid<96)
        float xpre[4] = {0.f, 0.f, 0.f, 0.f};
        if (tid < 96) {
            const float* xp = cd ? xpB : xpF;
            int tt = cd ? ttB : ttF;
            size_t base = ((size_t)((bb0 + cb) * S_ + tt)) * G4 + u0 + cu;
#pragma unroll
            for (int g = 0; g < 4; g++) xpre[g] = __ldg(xp + base + g * H_);
        }

#pragma unroll
        for (int d = 0; d < 2; d++) {
            if (step > 0) {
                // warp-autonomous poll of this warp's 4 producers for dir d
                unsigned target = 48u * (unsigned)step;
                if (lane < 4) {
                    const unsigned* f = &g_cnt[((d * 4 + bg) * 32 + (wrp << 2) + lane) * 8];
                    while (ld_relaxed(f) < target) { }
                }
                __syncwarp();
                asm volatile("fence.acq_rel.gpu;" ::: "memory");
                int tp = d ? (ttB + 1) : (ttF - 1);
                // stage this warp's k-range of h (4 batches x 48 k = 48 float4)
#pragma unroll
                for (int e = 0; e < 2; e++) {
                    int idx = lane + 32 * e;
                    if (idx < 48) {
                        int b  = idx / 12;
                        int c4 = (idx % 12) * 4;
                        int k  = wrp * 48 + c4;
                        const float4* src = (const float4*)(out +
                            ((size_t)((bb0 + b) * S_ + tp)) * 768 + d * H_ + k);
                        *(float4*)&s_h[(d * NBX + b) * HSTR + k] = __ldcg(src);
                    }
                }
                __syncwarp();
            }

            // mini-GEMM dir d: acc2[4b][3 row-pairs] over 12-k chunk
            unsigned long long acc2[NBX][3];
#pragma unroll
            for (int b = 0; b < NBX; b++)
#pragma unroll
                for (int rp = 0; rp < 3; rp++) acc2[b][rp] = 0ULL;

#pragma unroll
            for (int k4 = 0; k4 < 3; k4++) {
                float4 hv[NBX];
#pragma unroll
                for (int b = 0; b < NBX; b++)
                    hv[b] = *(const float4*)&s_h[(d * NBX + b) * HSTR + kbase + 4 * k4];
#pragma unroll
                for (int kk = 0; kk < 4; kk++) {
#pragma unroll
                    for (int b = 0; b < NBX; b++) {
                        float hs = (kk == 0) ? hv[b].x : (kk == 1) ? hv[b].y
                                 : (kk == 2) ? hv[b].z : hv[b].w;
                        unsigned long long h2 = pack2_(hs, hs);
#pragma unroll
                        for (int rp = 0; rp < 3; rp++)
                            fma2_(acc2[b][rp], h2, w2[d][rp][4 * k4 + kk]);
                    }
                }
            }
            // store partials (transposed + rotated, conflict-free)
            {
                float* pb = s_p + (d * 2 + buf) * PBUFD;
#pragma unroll
                for (int rp = 0; rp < 3; rp++) {
                    uint32_t qc = ((uint32_t)qg + (uint32_t)(rt * 3 + rp) * 4) & 31;
                    int ra = r0 + 2 * rp;
#pragma unroll
                    for (int b = 0; b < NBX; b++) {
                        float2 p = unpack2_(acc2[b][rp]);
                        float* row = pb + (b * 48 + ra) * 32;
                        row[qc]      = p.x;
                        row[32 + qc] = p.y;
                    }
                }
            }
        }
        __syncthreads();   // the ONLY block barrier per step-pair

        // gate combine: tid<48 -> F, tid in [48,96) -> B
        if (tid < 96) {
            const float* pbase = s_p + (cd * 2 + buf) * PBUFD + cb * 48 * 32;
            float gate[4];
#pragma unroll
            for (int g = 0; g < 4; g++) {
                int r = g * NUX + cu;
                const float* rowp = pbase + r * 32;
                uint32_t rot = (uint32_t)((r >> 1) * 4) & 31;
                float s0 = xpre[g], s1 = 0.f;
#pragma unroll
                for (int j = 0; j < 8; j += 2) {
                    float4 v0 = *(const float4*)(rowp + ((4 * j + rot) & 31));
                    float4 v1 = *(const float4*)(rowp + ((4 * j + 4 + rot) & 31));
                    s0 += (v0.x + v0.y) + (v0.z + v0.w);
                    s1 += (v1.x + v1.y) + (v1.z + v1.w);
                }
                gate[g] = s0 + s1;
            }
            float c = sigm_(gate[1]) * s_c[tid] + sigm_(gate[0]) * tanh_(gate[2]);
            s_c[tid] = c;
            float h = sigm_(gate[3]) * tanh_(c);
            int tt = cd ? ttB : ttF;
            __stcg(out + ((size_t)((bb0 + cb) * S_ + tt)) * 768 + cd * H_ + u0 + cu, h);
            red_release_add(mycnt);
        }
        buf ^= 1;
    }
}

// ---------------- windowed attention ----------------
__global__ __launch_bounds__(256) void attn_kernel(
    float* __restrict__ hcat, const float* __restrict__ attnW,
    const int* __restrict__ wsp)
{
    int gw   = (int)((blockIdx.x * blockDim.x + threadIdx.x) >> 5);
    int lane = threadIdx.x & 31;
    if (gw >= M_) return;
    int b = gw >> 10, i = gw & 1023;
    int Wn = wsp ? *wsp : 32;
    if (Wn < 0) Wn = 0;
    if (Wn > S_) Wn = S_;

    const float* w2 = attnW + H_;
    const float* w3 = attnW + 2 * H_;
    const float* hi = hcat + (size_t)gw * 768;

    float v[12], a[12];
#pragma unroll
    for (int q = 0; q < 12; q++) {
        int k = q * 32 + lane;
        v[q] = w2[k] + hi[k] * w3[k];
        a[q] = 0.f;
    }
    float m = -1e30f, Z = 0.f;
    int jlo = i - Wn; if (jlo < 0) jlo = 0;
    int jhi = i + Wn; if (jhi > S_ - 1) jhi = S_ - 1;

    for (int j = jlo; j <= jhi; j++) {
        const float* hj = hcat + ((size_t)(b * S_ + j)) * 768;
        float hq[12];
        float s = 0.f;
#pragma unroll
        for (int q = 0; q < 12; q++) {
            hq[q] = hj[q * 32 + lane];
            s = fmaf(v[q], hq[q], s);
        }
#pragma unroll
        for (int o = 16; o; o >>= 1) s += __shfl_xor_sync(0xffffffffu, s, o);
        float mn = fmaxf(m, s);
        float r  = __expf(m - mn);
        float e  = __expf(s - mn);
        Z = Z * r + e;
#pragma unroll
        for (int q = 0; q < 12; q++) a[q] = a[q] * r + e * hq[q];
        m = mn;
    }
    float inv = 1.f / Z;
#pragma unroll
    for (int q = 0; q < 12; q++)
        hcat[(size_t)gw * 768 + H_ + q * 32 + lane] = a[q] * inv;
}

// ---------------- final gemv ----------------
__global__ __launch_bounds__(256) void gemv_kernel(
    const float* __restrict__ A, const float* __restrict__ w,
    const float* __restrict__ b, float* __restrict__ out)
{
    int gw   = (int)((blockIdx.x * blockDim.x + threadIdx.x) >> 5);
    int lane = threadIdx.x & 31;
    if (gw >= M_) return;
    float s = 0.f;
#pragma unroll
    for (int k = lane; k < 96; k += 32) s = fmaf(A[(size_t)gw * 96 + k], w[k], s);
#pragma unroll
    for (int o = 16; o; o >>= 1) s += __shfl_xor_sync(0xffffffffu, s, o);
    if (lane == 0) out[gw] = s + b[0];
}

// ---------------- host ----------------
static int pick_by_size(const int* sizes, int n, int want, unsigned char* used)
{
    for (int i = 0; i < n; i++) {
        if (!used[i] && sizes[i] == want) { used[i] = 1; return i; }
    }
    return -1;
}

extern "C" void kernel_launch(void* const* d_in, const int* in_sizes, int n_in,
                              void* d_out, int out_size)
{
    unsigned char used[64];
    for (int i = 0; i < 64; i++) used[i] = 0;
    int ix[24];
    ix[0]  = pick_by_size(in_sizes, n_in, 12582912, used);
    ix[1]  = pick_by_size(in_sizes, n_in, 1179648,  used);
    ix[2]  = pick_by_size(in_sizes, n_in, 589824,   used);
    ix[3]  = pick_by_size(in_sizes, n_in, 1536,     used);
    ix[4]  = pick_by_size(in_sizes, n_in, 1179648,  used);
    ix[5]  = pick_by_size(in_sizes, n_in, 589824,   used);
    ix[6]  = pick_by_size(in_sizes, n_in, 1536,     used);
    ix[7]  = pick_by_size(in_sizes, n_in, 294912,   used);
    ix[8]  = pick_by_size(in_sizes, n_in, 384,      used);
    ix[9]  = pick_by_size(in_sizes, n_in, 1152,     used);
    ix[10] = pick_by_size(in_sizes, n_in, 1,        used);
    ix[11] = pick_by_size(in_sizes, n_in, 1179648,  used);
    ix[12] = pick_by_size(in_sizes, n_in, 589824,   used);
    ix[13] = pick_by_size(in_sizes, n_in, 1536,     used);
    ix[14] = pick_by_size(in_sizes, n_in, 1179648,  used);
    ix[15] = pick_by_size(in_sizes, n_in, 589824,   used);
    ix[16] = pick_by_size(in_sizes, n_in, 1536,     used);
    ix[17] = pick_by_size(in_sizes, n_in, 98304,    used);
    ix[18] = pick_by_size(in_sizes, n_in, 256,      used);
    ix[19] = pick_by_size(in_sizes, n_in, 24576,    used);
    ix[20] = pick_by_size(in_sizes, n_in, 96,       used);
    ix[21] = pick_by_size(in_sizes, n_in, 96,       used);
    ix[22] = pick_by_size(in_sizes, n_in, 1,        used);
    ix[23] = pick_by_size(in_sizes, n_in, 1,        used);

    bool ok = true;
    for (int i = 0; i < 23; i++) if (ix[i] < 0) ok = false;
    if (!ok) {
        for (int i = 0; i < 24; i++) ix[i] = (i < n_in) ? i : -1;
    }

    const float* x      = (const float*)d_in[ix[0]];
    const float* l1Wihf = (const float*)d_in[ix[1]];
    const float* l1Whhf = (const float*)d_in[ix[2]];
    const float* l1bf   = (const float*)d_in[ix[3]];
    const float* l1Wihb = (const float*)d_in[ix[4]];
    const float* l1Whhb = (const float*)d_in[ix[5]];
    const float* l1bb   = (const float*)d_in[ix[6]];
    const float* fc1W   = (const float*)d_in[ix[7]];
    const float* fc1b   = (const float*)d_in[ix[8]];
    const float* attnW  = (const float*)d_in[ix[9]];
    const float* l2Wihf = (const float*)d_in[ix[11]];
    const float* l2Whhf = (const float*)d_in[ix[12]];
    const float* l2bf   = (const float*)d_in[ix[13]];
    const float* l2Wihb = (const float*)d_in[ix[14]];
    const float* l2Whhb = (const float*)d_in[ix[15]];
    const float* l2bb   = (const float*)d_in[ix[16]];
    const float* W1     = (const float*)d_in[ix[17]];
    const float* b1     = (const float*)d_in[ix[18]];
    const float* W2     = (const float*)d_in[ix[19]];
    const float* b2     = (const float*)d_in[ix[20]];
    const float* W3     = (const float*)d_in[ix[21]];
    const float* b3     = (const float*)d_in[ix[22]];
    const int*   wsp    = (ix[23] >= 0) ? (const int*)d_in[ix[23]] : nullptr;

    float *xpF, *xpB, *lstm, *hcat, *h2, *mlp1, *mlp2;
    __nv_bfloat16 *A2, *W2b;
    cudaGetSymbolAddress((void**)&xpF,  g_xprojF);
    cudaGetSymbolAddress((void**)&xpB,  g_xprojB);
    cudaGetSymbolAddress((void**)&lstm, g_lstm);
    cudaGetSymbolAddress((void**)&hcat, g_hcat);
    cudaGetSymbolAddress((void**)&h2,   g_h2);
    cudaGetSymbolAddress((void**)&mlp1, g_mlp1);
    cudaGetSymbolAddress((void**)&mlp2, g_mlp2);
    cudaGetSymbolAddress((void**)&A2,   g_A2);
    cudaGetSymbolAddress((void**)&W2b,  g_W2);

    size_t lsm = (size_t)(2 * NBX * HSTR + 4 * PBUFD + 96) * sizeof(float);
    cudaFuncSetAttribute(lstm_scan_kernel,
                         cudaFuncAttributeMaxDynamicSharedMemorySize, (int)lsm);
    size_t tgsm = 65536;
    cudaFuncSetAttribute(tgemm_kernel,
                         cudaFuncAttributeMaxDynamicSharedMemorySize, (int)tgsm);

    const int APQ   = M_ * 192;
    const int WPQ   = G4 * 192;
    const int FC1PQ = H_ * 192;
    dim3 tg_grid(G4 / 128, M_ / 128);       // xproj: 12 x 128
    dim3 fc_grid(H_ / 128, M_ / 128);       // fc1:    3 x 128

    // ---- layer 1: split preps + tensor xproj ----
    split_prep_kernel<<<(APQ + 255) / 256, 256>>>(x, A2, APQ, 0);
    split_prep_kernel<<<(WPQ + 255) / 256, 256>>>(l1Wihf, W2b, WPQ, 1);
    tgemm_kernel<<<tg_grid, 256, tgsm>>>(A2, W2b, l1bf, xpF, G4);
    split_prep_kernel<<<(WPQ + 255) / 256, 256>>>(l1Wihb, W2b, WPQ, 1);
    tgemm_kernel<<<tg_grid, 256, tgsm>>>(A2, W2b, l1bb, xpB, G4);
    flags_zero_kernel<<<1, 256>>>();
    lstm_scan_kernel<<<NCTA, TPB, lsm>>>(xpF, xpB, l1Whhf, l1Whhb, lstm);

    // fc1 (tensor) -> h (first half of hcat, ldc=768)
    split_prep_kernel<<<(APQ + 255) / 256, 256>>>(lstm, A2, APQ, 0);
    split_prep_kernel<<<(FC1PQ + 255) / 256, 256>>>(fc1W, W2b, FC1PQ, 1);
    tgemm_kernel<<<fc_grid, 256, tgsm>>>(A2, W2b, fc1b, hcat, 768);

    // windowed attention -> second half of hcat
    attn_kernel<<<M_ / 8, 256>>>(hcat, attnW, wsp);

    // ---- layer 2 ----
    split_prep_kernel<<<(APQ + 255) / 256, 256>>>(hcat, A2, APQ, 0);
    split_prep_kernel<<<(WPQ + 255) / 256, 256>>>(l2Wihf, W2b, WPQ, 1);
    tgemm_kernel<<<tg_grid, 256, tgsm>>>(A2, W2b, l2bf, xpF, G4);
    split_prep_kernel<<<(WPQ + 255) / 256, 256>>>(l2Wihb, W2b, WPQ, 1);
    tgemm_kernel<<<tg_grid, 256, tgsm>>>(A2, W2b, l2bb, xpB, G4);
    flags_zero_kernel<<<1, 256>>>();
    lstm_scan_kernel<<<NCTA, TPB, lsm>>>(xpF, xpB, l2Whhf, l2Whhb, lstm);

    // fc1 again (tensor) -> h2 (ldc=384)
    split_prep_kernel<<<(APQ + 255) / 256, 256>>>(lstm, A2, APQ, 0);
    split_prep_kernel<<<(FC1PQ + 255) / 256, 256>>>(fc1W, W2b, FC1PQ, 1);
    tgemm_kernel<<<fc_grid, 256, tgsm>>>(A2, W2b, fc1b, h2, H_);

    // MLP head
    gemm_bias_kernel<1><<<dim3(2, M_ / 128), 256>>>(h2,   W1, b1, mlp1, M_, 256, H_,  256);
    gemm_bias_kernel<1><<<dim3(1, M_ / 128), 256>>>(mlp1, W2, b2, mlp2, M_, 96,  256, 96);
    gemv_kernel<<<M_ / 8, 256>>>(mlp2, W3, b3, (float*)d_out);
}

// round 14
// speedup vs baseline: 1.4371x; 1.4371x over previous
#include <cuda_runtime.h>
#include <cuda_bf16.h>
#include <cstdint>
#include <cstddef>

// Problem dims
#define B_   16
#define S_   1024
#define D_   768
#define H_   384
#define G4   1536          // 4*H
#define G8   3072          // both dirs
#define M_   16384         // B*S
#define K2   2304          // split-GEMM K'' = 3*768

// ---------------- scratch (static device allocations, 256B aligned) ----------------
__device__ __align__(256) float g_xpAll [(size_t)M_ * G8];   // [M][3072]: F 0:1536, B 1536:3072
__device__ __align__(256) float g_lstm  [(size_t)M_ * 768];
__device__ __align__(256) float g_hcat  [(size_t)M_ * 768];
__device__ __align__(256) float g_h2    [(size_t)M_ * H_];
__device__ __align__(256) float g_mlp1  [(size_t)M_ * 256];
__device__ __align__(256) float g_mlp2  [(size_t)M_ * 96];
__device__ __align__(256) __nv_bfloat16 g_A2 [(size_t)M_ * K2];   // split A
__device__ __align__(256) __nv_bfloat16 g_W2 [(size_t)G8 * K2];   // split W (both dirs)
__device__ __align__(256) __nv_bfloat16 g_Wfc[(size_t)H_ * K2];   // split fc1W (prepped once)
// dataflow step-counters: 128 producers (4 cliques x 32), 32B stride
__device__ __align__(256) unsigned g_cnt[128 * 8];

// ---------------- packed f32x2 helpers ----------------
__device__ __forceinline__ void fma2_(unsigned long long& d,
                                      unsigned long long a,
                                      unsigned long long b) {
    asm("fma.rn.f32x2 %0, %1, %2, %0;" : "+l"(d) : "l"(a), "l"(b));
}
__device__ __forceinline__ unsigned long long pack2_(float x, float y) {
    unsigned long long d;
    asm("mov.b64 %0, {%1, %2};" : "=l"(d) : "f"(x), "f"(y));
    return d;
}
__device__ __forceinline__ float2 unpack2_(unsigned long long v) {
    float2 r;
    asm("mov.b64 {%0, %1}, %2;" : "=f"(r.x), "=f"(r.y) : "l"(v));
    return r;
}

// ---------------- generic SIMT GEMM (MLP head) ----------------
template<int ACT>
__global__ __launch_bounds__(256, 2) void gemm_bias_kernel(
    const float* __restrict__ A, const float* __restrict__ W,
    const float* __restrict__ bias, float* __restrict__ C,
    int M, int N, int K, int ldc)
{
    __shared__ float sA[16][132];
    __shared__ float sB[16][132];
    int tid = threadIdx.x;
    int m0 = blockIdx.y * 128;
    int n0 = blockIdx.x * 128;
    int tx = tid & 15, ty = tid >> 4;

    unsigned long long acc2[8][4];
#pragma unroll
    for (int i = 0; i < 8; i++)
#pragma unroll
        for (int j = 0; j < 4; j++) acc2[i][j] = 0ULL;

    for (int k0 = 0; k0 < K; k0 += 16) {
#pragma unroll
        for (int e = 0; e < 2; e++) {
            int f4 = tid + 256 * e;
            int r  = f4 >> 2;
            int c4 = (f4 & 3) << 2;
            float4 av = *(const float4*)(A + (size_t)(m0 + r) * K + k0 + c4);
            sA[c4 + 0][r] = av.x; sA[c4 + 1][r] = av.y;
            sA[c4 + 2][r] = av.z; sA[c4 + 3][r] = av.w;
            int n = n0 + r;
            float4 wv = make_float4(0.f, 0.f, 0.f, 0.f);
            if (n < N) wv = *(const float4*)(W + (size_t)n * K + k0 + c4);
            sB[c4 + 0][r] = wv.x; sB[c4 + 1][r] = wv.y;
            sB[c4 + 2][r] = wv.z; sB[c4 + 3][r] = wv.w;
        }
        __syncthreads();
#pragma unroll
        for (int kk = 0; kk < 16; kk++) {
            float a[8];
            *(float4*)&a[0] = *(const float4*)&sA[kk][ty * 8];
            *(float4*)&a[4] = *(const float4*)&sA[kk][ty * 8 + 4];
            ulonglong2 bv0 = *(const ulonglong2*)&sB[kk][tx * 8];
            ulonglong2 bv1 = *(const ulonglong2*)&sB[kk][tx * 8 + 4];
            unsigned long long b2[4] = {bv0.x, bv0.y, bv1.x, bv1.y};
#pragma unroll
            for (int i = 0; i < 8; i++) {
                unsigned long long a2 = pack2_(a[i], a[i]);
#pragma unroll
                for (int j = 0; j < 4; j++)
                    fma2_(acc2[i][j], a2, b2[j]);
            }
        }
        __syncthreads();
    }

#pragma unroll
    for (int i = 0; i < 8; i++) {
        int m = m0 + ty * 8 + i;
#pragma unroll
        for (int j2 = 0; j2 < 4; j2++) {
            float2 p = unpack2_(acc2[i][j2]);
            int n = n0 + tx * 8 + j2 * 2;
            if (n < N) {
                float v0 = p.x + bias[n];
                if (ACT) v0 = fmaxf(v0, 0.f);
                C[(size_t)m * ldc + n] = v0;
            }
            if (n + 1 < N) {
                float v1 = p.y + bias[n + 1];
                if (ACT) v1 = fmaxf(v1, 0.f);
                C[(size_t)m * ldc + n + 1] = v1;
            }
        }
    }
}

// ---------------- bf16 split prep ----------------
// mode 0 (A): [hi | hi | lo]     mode 1 (W): [hi | lo | hi]
__global__ __launch_bounds__(256) void split_prep_kernel(
    const float* __restrict__ in, __nv_bfloat16* __restrict__ out,
    int nquads, int mode)
{
    int g = blockIdx.x * blockDim.x + threadIdx.x;
    if (g >= nquads) return;
    int m = g / 192;
    int q = (g % 192) * 4;
    float4 v = *(const float4*)(in + (size_t)m * 768 + q);
    float a[4] = {v.x, v.y, v.z, v.w};
    float h0 = __bfloat162float(__float2bfloat16(a[0]));
    float h1 = __bfloat162float(__float2bfloat16(a[1]));
    float h2 = __bfloat162float(__float2bfloat16(a[2]));
    float h3 = __bfloat162float(__float2bfloat16(a[3]));
    __nv_bfloat162 hi01 = __nv_bfloat162(__float2bfloat16(a[0]), __float2bfloat16(a[1]));
    __nv_bfloat162 hi23 = __nv_bfloat162(__float2bfloat16(a[2]), __float2bfloat16(a[3]));
    __nv_bfloat162 lo01 = __nv_bfloat162(__float2bfloat16(a[0] - h0), __float2bfloat16(a[1] - h1));
    __nv_bfloat162 lo23 = __nv_bfloat162(__float2bfloat16(a[2] - h2), __float2bfloat16(a[3] - h3));
    __nv_bfloat16* o = out + (size_t)m * K2 + q;
    *(__nv_bfloat162*)(o + 0) = hi01;  *(__nv_bfloat162*)(o + 2) = hi23;
    if (mode == 0) {
        *(__nv_bfloat162*)(o + 768)  = hi01;  *(__nv_bfloat162*)(o + 770)  = hi23;
        *(__nv_bfloat162*)(o + 1536) = lo01;  *(__nv_bfloat162*)(o + 1538) = lo23;
    } else {
        *(__nv_bfloat162*)(o + 768)  = lo01;  *(__nv_bfloat162*)(o + 770)  = lo23;
        *(__nv_bfloat162*)(o + 1536) = hi01;  *(__nv_bfloat162*)(o + 1538) = hi23;
    }
}

// ---------------- warp-MMA bf16 GEMM: C[M,N] = A2 @ W2^T + bias ----------------
// Bias split: blocks with blockIdx.x < nsplit use biasA[col], else biasB[col - 128*nsplit].
#define TG_NBLK 36          // K2 / 64

__device__ __forceinline__ uint32_t smem_u32_(const void* p) {
    uint32_t a;
    asm("{ .reg .u64 t; cvta.to.shared.u64 t, %1; cvt.u32.u64 %0, t; }" : "=r"(a) : "l"(p));
    return a;
}
__device__ __forceinline__ uint32_t swz_(uint32_t off) {
    return off ^ ((off >> 3) & 0x70);
}
__device__ __forceinline__ void cp16_(uint32_t s, const void* g) {
    asm volatile("cp.async.cg.shared.global [%0], [%1], 16;" :: "r"(s), "l"(g) : "memory");
}
#define LDSM4_(d0, d1, d2, d3, addr) \
    asm volatile("ldmatrix.sync.aligned.m8n8.x4.shared.b16 {%0,%1,%2,%3}, [%4];" \
                 : "=r"(d0), "=r"(d1), "=r"(d2), "=r"(d3) : "r"(addr))
#define MMA16816_(c, a, b0, b1) \
    asm volatile("mma.sync.aligned.m16n8k16.row.col.f32.bf16.bf16.f32 " \
                 "{%0,%1,%2,%3}, {%4,%5,%6,%7}, {%8,%9}, {%0,%1,%2,%3};" \
                 : "+f"((c)[0]), "+f"((c)[1]), "+f"((c)[2]), "+f"((c)[3]) \
                 : "r"((a)[0]), "r"((a)[1]), "r"((a)[2]), "r"((a)[3]), \
                   "r"(b0), "r"(b1))

__global__ __launch_bounds__(256) void tgemm_kernel(
    const __nv_bfloat16* __restrict__ A2,
    const __nv_bfloat16* __restrict__ W2,
    const float* __restrict__ biasA,
    const float* __restrict__ biasB,
    int nsplit,
    float* __restrict__ C, int ldc)
{
    extern __shared__ char smraw[];
    uint32_t sb = smem_u32_(smraw);
    int tid  = threadIdx.x;
    int wid  = tid >> 5;
    int lane = tid & 31;
    int n0 = blockIdx.x * 128;
    int m0 = blockIdx.y * 128;
    int wm = (wid & 3) * 32;
    int wn = (wid >> 2) * 64;

    const float* bp = ((int)blockIdx.x < nsplit) ? biasA : biasB;
    int coff = ((int)blockIdx.x < nsplit) ? 0 : nsplit * 128;

    float acc[2][8][4];
#pragma unroll
    for (int mt = 0; mt < 2; mt++)
#pragma unroll
        for (int nt = 0; nt < 8; nt++)
#pragma unroll
            for (int e = 0; e < 4; e++) acc[mt][nt][e] = 0.f;

    int arow = wm + (lane & 15);
    uint32_t arowoff = (uint32_t)arow * 128;
    uint32_t amask   = (uint32_t)(arow & 7) << 4;
    uint32_t akh     = (uint32_t)(lane >> 4) * 16;

    int brow = wn + (lane & 7) + ((lane >> 4) << 3);
    uint32_t browoff = (uint32_t)brow * 128;
    uint32_t bmask   = (uint32_t)(brow & 7) << 4;
    uint32_t bkh     = (uint32_t)((lane >> 3) & 1) * 16;

#pragma unroll
    for (int i = 0; i < 4; i++) {
        int cid = tid + 256 * i;
        int row = cid >> 3, ch = cid & 7;
        uint32_t so = swz_((uint32_t)row * 128 + (uint32_t)ch * 16);
        cp16_(sb + so,           A2 + (size_t)(m0 + row) * K2 + ch * 8);
        cp16_(sb + 32768 + so,   W2 + (size_t)(n0 + row) * K2 + ch * 8);
    }
    asm volatile("cp.async.commit_group;" ::: "memory");

    for (int blk = 0; blk < TG_NBLK; blk++) {
        int bufc = blk & 1;
        if (blk + 1 < TG_NBLK) {
            int bufn = (blk + 1) & 1;
            size_t gk = (size_t)(blk + 1) * 64;
#pragma unroll
            for (int i = 0; i < 4; i++) {
                int cid = tid + 256 * i;
                int row = cid >> 3, ch = cid & 7;
                uint32_t so = swz_((uint32_t)row * 128 + (uint32_t)ch * 16);
                cp16_(sb + bufn * 16384 + so,
                      A2 + (size_t)(m0 + row) * K2 + gk + ch * 8);
                cp16_(sb + 32768 + bufn * 16384 + so,
                      W2 + (size_t)(n0 + row) * K2 + gk + ch * 8);
            }
            asm volatile("cp.async.commit_group;" ::: "memory");
            asm volatile("cp.async.wait_group 1;" ::: "memory");
        } else {
            asm volatile("cp.async.wait_group 0;" ::: "memory");
        }
        __syncthreads();

        uint32_t abuf = sb + bufc * 16384;
        uint32_t bbuf = sb + 32768 + bufc * 16384;
#pragma unroll
        for (int kk = 0; kk < 4; kk++) {
            uint32_t acol = (akh + (uint32_t)kk * 32) ^ amask;
            uint32_t bcol = (bkh + (uint32_t)kk * 32) ^ bmask;
            uint32_t a[2][4], b[4][4];
#pragma unroll
            for (int mt = 0; mt < 2; mt++)
                LDSM4_(a[mt][0], a[mt][1], a[mt][2], a[mt][3],
                       abuf + arowoff + mt * 2048 + acol);
#pragma unroll
            for (int g = 0; g < 4; g++)
                LDSM4_(b[g][0], b[g][1], b[g][2], b[g][3],
                       bbuf + browoff + g * 2048 + bcol);
#pragma unroll
            for (int mt = 0; mt < 2; mt++)
#pragma unroll
                for (int nt = 0; nt < 8; nt++) {
                    int g = nt >> 1, h = (nt & 1) * 2;
                    MMA16816_(acc[mt][nt], a[mt], b[g][h], b[g][h + 1]);
                }
        }
        __syncthreads();
    }

#pragma unroll
    for (int mt = 0; mt < 2; mt++)
#pragma unroll
        for (int nt = 0; nt < 8; nt++) {
            int row = m0 + wm + mt * 16 + (lane >> 2);
            int col = n0 + wn + nt * 8 + (lane & 3) * 2;
            float2 bv = *(const float2*)(bp + (col - coff));
            float2 o0 = make_float2(acc[mt][nt][0] + bv.x, acc[mt][nt][1] + bv.y);
            float2 o1 = make_float2(acc[mt][nt][2] + bv.x, acc[mt][nt][3] + bv.y);
            *(float2*)(C + (size_t)row * ldc + col) = o0;
            *(float2*)(C + (size_t)(row + 8) * ldc + col) = o1;
        }
}

// ---------------- LSTM recurrent scan (R12: warp-autonomous, Whh in registers) ----------------
// s_p: per gate-row transposed with 4-float rotation; combine reads float4 cyclic.
#define NUX   12
#define NBX   8
#define HSTR  392
#define PBUF  (NBX * 48 * 32)    // 12288 floats per buffer
#define NCTA  128
#define TPB   256

__device__ __forceinline__ float sigm_(float x) { return 1.f / (1.f + __expf(-x)); }
__device__ __forceinline__ float tanh_(float x) {
    float t = __expf(-2.f * fabsf(x));
    float r = (1.f - t) / (1.f + t);
    return x < 0.f ? -r : r;
}
__device__ __forceinline__ void red_release_add(unsigned* p) {
    asm volatile("red.release.gpu.global.add.u32 [%0], %1;" :: "l"(p), "r"(1u) : "memory");
}
__device__ __forceinline__ unsigned ld_relaxed(const unsigned* p) {
    unsigned v;
    asm volatile("ld.relaxed.gpu.global.u32 %0, [%1];" : "=r"(v) : "l"(p) : "memory");
    return v;
}

__global__ void flags_zero_kernel()
{
    g_cnt[threadIdx.x * 8] = 0u;
}

__global__ __launch_bounds__(TPB, 1) void lstm_scan_kernel(
    const float* __restrict__ xpAll,   // [M][3072], dir offset 1536
    const float* __restrict__ WhhF, const float* __restrict__ WhhB,
    float* __restrict__ out)
{
    extern __shared__ float sm[];
    float* s_h = sm;
    float* s_p = s_h + NBX * HSTR;
    float* s_c = s_p + 2 * PBUF;

    int tid  = threadIdx.x;
    int wrp  = tid >> 5;
    int lane = tid & 31;
    int dir = blockIdx.x >> 6;
    int bg  = (blockIdx.x >> 5) & 1;
    int ug  = blockIdx.x & 31;
    int u0  = ug * NUX;
    int bb0 = bg * NBX;
    int clique = dir * 2 + bg;
    const float* Whh = dir ? WhhB : WhhF;

    int ql    = lane & 3;
    int rt    = lane >> 2;
    int kbase = wrp * 48 + ql * 12;
    int r0    = rt * 6;
    int qg    = wrp * 4 + ql;

    unsigned long long w2[3][12];
#pragma unroll
    for (int rp = 0; rp < 3; rp++) {
        int ra = r0 + 2 * rp, rb = ra + 1;
        const float* Wa = Whh + (size_t)((ra / NUX) * H_ + u0 + (ra % NUX)) * H_ + kbase;
        const float* Wb = Whh + (size_t)((rb / NUX) * H_ + u0 + (rb % NUX)) * H_ + kbase;
#pragma unroll
        for (int k = 0; k < 12; k++)
            w2[rp][k] = pack2_(__ldg(Wa + k), __ldg(Wb + k));
    }
    if (tid < NBX * NUX) s_c[tid] = 0.f;

    {
        int kw = wrp * 48;
#pragma unroll
        for (int e = 0; e < 3; e++) {
            int idx = lane + 32 * e;
            int b   = idx / 12;
            int c4  = (idx % 12) * 4;
            *(float4*)&s_h[b * HSTR + kw + c4] = make_float4(0.f, 0.f, 0.f, 0.f);
        }
    }
    __syncthreads();

    unsigned* mycnt = &g_cnt[(clique * 32 + ug) * 8];
    int cb = tid / NUX, cu = tid % NUX;
    int buf = 0;

    for (int step = 0; step < S_; step++) {
        int tt = dir ? (S_ - 1 - step) : step;

        float xpre[4] = {0.f, 0.f, 0.f, 0.f};
        if (tid < NBX * NUX) {
            size_t base = ((size_t)((bb0 + cb) * S_ + tt)) * G8 + (size_t)dir * G4 + u0 + cu;
#pragma unroll
            for (int g = 0; g < 4; g++) xpre[g] = __ldg(xpAll + base + g * H_);
        }

        if (step > 0) {
            unsigned target = 96u * (unsigned)step;
            if (lane < 4) {
                const unsigned* f = &g_cnt[(clique * 32 + (wrp << 2) + lane) * 8];
                while (ld_relaxed(f) < target) { }
            }
            __syncwarp();
            asm volatile("fence.acq_rel.gpu;" ::: "memory");
            int tp = dir ? (tt + 1) : (tt - 1);
            int kw = wrp * 48;
#pragma unroll
            for (int e = 0; e < 3; e++) {
                int idx = lane + 32 * e;
                int b   = idx / 12;
                int c4  = (idx % 12) * 4;
                int k   = kw + c4;
                const float4* src = (const float4*)(out +
                    ((size_t)((bb0 + b) * S_ + tp)) * 768 + dir * H_ + k);
                *(float4*)&s_h[b * HSTR + k] = __ldcg(src);
            }
            __syncwarp();
        }

        unsigned long long acc2[NBX][3];
#pragma unroll
        for (int b = 0; b < NBX; b++)
#pragma unroll
            for (int rp = 0; rp < 3; rp++) acc2[b][rp] = 0ULL;

#pragma unroll
        for (int k4 = 0; k4 < 3; k4++) {
            float4 hv[NBX];
#pragma unroll
            for (int b = 0; b < NBX; b++)
                hv[b] = *(const float4*)&s_h[b * HSTR + kbase + 4 * k4];
#pragma unroll
            for (int kk = 0; kk < 4; kk++) {
#pragma unroll
                for (int b = 0; b < NBX; b++) {
                    float hs = (kk == 0) ? hv[b].x : (kk == 1) ? hv[b].y
                             : (kk == 2) ? hv[b].z : hv[b].w;
                    unsigned long long h2 = pack2_(hs, hs);
#pragma unroll
                    for (int rp = 0; rp < 3; rp++)
                        fma2_(acc2[b][rp], h2, w2[rp][4 * k4 + kk]);
                }
            }
        }
        {
            float* pb = s_p + buf * PBUF;
#pragma unroll
            for (int rp = 0; rp < 3; rp++) {
                uint32_t qc = ((uint32_t)qg + (uint32_t)(rt * 3 + rp) * 4) & 31;
                int ra = r0 + 2 * rp;
#pragma unroll
                for (int b = 0; b < NBX; b++) {
                    float2 p = unpack2_(acc2[b][rp]);
                    float* row = pb + (b * 48 + ra) * 32;
                    row[qc]      = p.x;
                    row[32 + qc] = p.y;
                }
            }
        }
        __syncthreads();

        if (tid < NBX * NUX) {
            const float* pbase = s_p + buf * PBUF + cb * 48 * 32;
            float gate[4];
#pragma unroll
            for (int g = 0; g < 4; g++) {
                int r = g * NUX + cu;
                const float* rowp = pbase + r * 32;
                uint32_t rot = (uint32_t)((r >> 1) * 4) & 31;
                float s0 = xpre[g], s1 = 0.f;
#pragma unroll
                for (int j = 0; j < 8; j += 2) {
                    float4 v0 = *(const float4*)(rowp + ((4 * j + rot) & 31));
                    float4 v1 = *(const float4*)(rowp + ((4 * j + 4 + rot) & 31));
                    s0 += (v0.x + v0.y) + (v0.z + v0.w);
                    s1 += (v1.x + v1.y) + (v1.z + v1.w);
                }
                gate[g] = s0 + s1;
            }
            float c = sigm_(gate[1]) * s_c[tid] + sigm_(gate[0]) * tanh_(gate[2]);
            s_c[tid] = c;
            float h = sigm_(gate[3]) * tanh_(c);
            __stcg(out + ((size_t)((bb0 + cb) * S_ + tt)) * 768 + dir * H_ + u0 + cu, h);
            red_release_add(mycnt);
        }
        buf ^= 1;
    }
}

// ---------------- windowed attention ----------------
__global__ __launch_bounds__(256) void attn_kernel(
    float* __restrict__ hcat, const float* __restrict__ attnW,
    const int* __restrict__ wsp)
{
    int gw   = (int)((blockIdx.x * blockDim.x + threadIdx.x) >> 5);
    int lane = threadIdx.x & 31;
    if (gw >= M_) return;
    int b = gw >> 10, i = gw & 1023;
    int Wn = wsp ? *wsp : 32;
    if (Wn < 0) Wn = 0;
    if (Wn > S_) Wn = S_;

    const float* w2 = attnW + H_;
    const float* w3 = attnW + 2 * H_;
    const float* hi = hcat + (size_t)gw * 768;

    float v[12], a[12];
#pragma unroll
    for (int q = 0; q < 12; q++) {
        int k = q * 32 + lane;
        v[q] = w2[k] + hi[k] * w3[k];
        a[q] = 0.f;
    }
    float m = -1e30f, Z = 0.f;
    int jlo = i - Wn; if (jlo < 0) jlo = 0;
    int jhi = i + Wn; if (jhi > S_ - 1) jhi = S_ - 1;

    for (int j = jlo; j <= jhi; j++) {
        const float* hj = hcat + ((size_t)(b * S_ + j)) * 768;
        float hq[12];
        float s = 0.f;
#pragma unroll
        for (int q = 0; q < 12; q++) {
            hq[q] = hj[q * 32 + lane];
            s = fmaf(v[q], hq[q], s);
        }
#pragma unroll
        for (int o = 16; o; o >>= 1) s += __shfl_xor_sync(0xffffffffu, s, o);
        float mn = fmaxf(m, s);
        float r  = __expf(m - mn);
        float e  = __expf(s - mn);
        Z = Z * r + e;
#pragma unroll
        for (int q = 0; q < 12; q++) a[q] = a[q] * r + e * hq[q];
        m = mn;
    }
    float inv = 1.f / Z;
#pragma unroll
    for (int q = 0; q < 12; q++)
        hcat[(size_t)gw * 768 + H_ + q * 32 + lane] = a[q] * inv;
}

// ---------------- final gemv ----------------
__global__ __launch_bounds__(256) void gemv_kernel(
    const float* __restrict__ A, const float* __restrict__ w,
    const float* __restrict__ b, float* __restrict__ out)
{
    int gw   = (int)((blockIdx.x * blockDim.x + threadIdx.x) >> 5);
    int lane = threadIdx.x & 31;
    if (gw >= M_) return;
    float s = 0.f;
#pragma unroll
    for (int k = lane; k < 96; k += 32) s = fmaf(A[(size_t)gw * 96 + k], w[k], s);
#pragma unroll
    for (int o = 16; o; o >>= 1) s += __shfl_xor_sync(0xffffffffu, s, o);
    if (lane == 0) out[gw] = s + b[0];
}

// ---------------- host ----------------
static int pick_by_size(const int* sizes, int n, int want, unsigned char* used)
{
    for (int i = 0; i < n; i++) {
        if (!used[i] && sizes[i] == want) { used[i] = 1; return i; }
    }
    return -1;
}

extern "C" void kernel_launch(void* const* d_in, const int* in_sizes, int n_in,
                              void* d_out, int out_size)
{
    unsigned char used[64];
    for (int i = 0; i < 64; i++) used[i] = 0;
    int ix[24];
    ix[0]  = pick_by_size(in_sizes, n_in, 12582912, used);
    ix[1]  = pick_by_size(in_sizes, n_in, 1179648,  used);
    ix[2]  = pick_by_size(in_sizes, n_in, 589824,   used);
    ix[3]  = pick_by_size(in_sizes, n_in, 1536,     used);
    ix[4]  = pick_by_size(in_sizes, n_in, 1179648,  used);
    ix[5]  = pick_by_size(in_sizes, n_in, 589824,   used);
    ix[6]  = pick_by_size(in_sizes, n_in, 1536,     used);
    ix[7]  = pick_by_size(in_sizes, n_in, 294912,   used);
    ix[8]  = pick_by_size(in_sizes, n_in, 384,      used);
    ix[9]  = pick_by_size(in_sizes, n_in, 1152,     used);
    ix[10] = pick_by_size(in_sizes, n_in, 1,        used);
    ix[11] = pick_by_size(in_sizes, n_in, 1179648,  used);
    ix[12] = pick_by_size(in_sizes, n_in, 589824,   used);
    ix[13] = pick_by_size(in_sizes, n_in, 1536,     used);
    ix[14] = pick_by_size(in_sizes, n_in, 1179648,  used);
    ix[15] = pick_by_size(in_sizes, n_in, 589824,   used);
    ix[16] = pick_by_size(in_sizes, n_in, 1536,     used);
    ix[17] = pick_by_size(in_sizes, n_in, 98304,    used);
    ix[18] = pick_by_size(in_sizes, n_in, 256,      used);
    ix[19] = pick_by_size(in_sizes, n_in, 24576,    used);
    ix[20] = pick_by_size(in_sizes, n_in, 96,       used);
    ix[21] = pick_by_size(in_sizes, n_in, 96,       used);
    ix[22] = pick_by_size(in_sizes, n_in, 1,        used);
    ix[23] = pick_by_size(in_sizes, n_in, 1,        used);

    bool ok = true;
    for (int i = 0; i < 23; i++) if (ix[i] < 0) ok = false;
    if (!ok) {
        for (int i = 0; i < 24; i++) ix[i] = (i < n_in) ? i : -1;
    }

    const float* x      = (const float*)d_in[ix[0]];
    const float* l1Wihf = (const float*)d_in[ix[1]];
    const float* l1Whhf = (const float*)d_in[ix[2]];
    const float* l1bf   = (const float*)d_in[ix[3]];
    const float* l1Wihb = (const float*)d_in[ix[4]];
    const float* l1Whhb = (const float*)d_in[ix[5]];
    const float* l1bb   = (const float*)d_in[ix[6]];
    const float* fc1W   = (const float*)d_in[ix[7]];
    const float* fc1b   = (const float*)d_in[ix[8]];
    const float* attnW  = (const float*)d_in[ix[9]];
    const float* l2Wihf = (const float*)d_in[ix[11]];
    const float* l2Whhf = (const float*)d_in[ix[12]];
    const float* l2bf   = (const float*)d_in[ix[13]];
    const float* l2Wihb = (const float*)d_in[ix[14]];
    const float* l2Whhb = (const float*)d_in[ix[15]];
    const float* l2bb   = (const float*)d_in[ix[16]];
    const float* W1     = (const float*)d_in[ix[17]];
    const float* b1     = (const float*)d_in[ix[18]];
    const float* W2     = (const float*)d_in[ix[19]];
    const float* b2     = (const float*)d_in[ix[20]];
    const float* W3     = (const float*)d_in[ix[21]];
    const float* b3     = (const float*)d_in[ix[22]];
    const int*   wsp    = (ix[23] >= 0) ? (const int*)d_in[ix[23]] : nullptr;

    float *xpAll, *lstm, *hcat, *h2, *mlp1, *mlp2;
    __nv_bfloat16 *A2, *W2b, *Wfc;
    cudaGetSymbolAddress((void**)&xpAll, g_xpAll);
    cudaGetSymbolAddress((void**)&lstm,  g_lstm);
    cudaGetSymbolAddress((void**)&hcat,  g_hcat);
    cudaGetSymbolAddress((void**)&h2,    g_h2);
    cudaGetSymbolAddress((void**)&mlp1,  g_mlp1);
    cudaGetSymbolAddress((void**)&mlp2,  g_mlp2);
    cudaGetSymbolAddress((void**)&A2,    g_A2);
    cudaGetSymbolAddress((void**)&W2b,   g_W2);
    cudaGetSymbolAddress((void**)&Wfc,   g_Wfc);

    size_t lsm = (size_t)(NBX * HSTR + 2 * PBUF + NBX * NUX) * sizeof(float);
    cudaFuncSetAttribute(lstm_scan_kernel,
                         cudaFuncAttributeMaxDynamicSharedMemorySize, (int)lsm);
    size_t tgsm = 65536;
    cudaFuncSetAttribute(tgemm_kernel,
                         cudaFuncAttributeMaxDynamicSharedMemorySize, (int)tgsm);

    const int APQ   = M_ * 192;
    const int WPQ   = G4 * 192;
    const int FC1PQ = H_ * 192;
    dim3 xp_grid(G8 / 128, M_ / 128);       // combined xproj: 24 x 128
    dim3 fc_grid(H_ / 128, M_ / 128);       // fc1: 3 x 128

    // fc1W prepped ONCE (reused by both fc1 GEMMs)
    split_prep_kernel<<<(FC1PQ + 255) / 256, 256>>>(fc1W, Wfc, FC1PQ, 1);

    // ---- layer 1: A prep + both weight preps + ONE combined xproj GEMM ----
    split_prep_kernel<<<(APQ + 255) / 256, 256>>>(x, A2, APQ, 0);
    split_prep_kernel<<<(WPQ + 255) / 256, 256>>>(l1Wihf, W2b, WPQ, 1);
    split_prep_kernel<<<(WPQ + 255) / 256, 256>>>(l1Wihb, W2b + (size_t)G4 * K2, WPQ, 1);
    tgemm_kernel<<<xp_grid, 256, tgsm>>>(A2, W2b, l1bf, l1bb, 12, xpAll, G8);
    flags_zero_kernel<<<1, 128>>>();
    lstm_scan_kernel<<<NCTA, TPB, lsm>>>(xpAll, l1Whhf, l1Whhb, lstm);

    // fc1 (tensor) -> h (first half of hcat, ldc=768)
    split_prep_kernel<<<(APQ + 255) / 256, 256>>>(lstm, A2, APQ, 0);
    tgemm_kernel<<<fc_grid, 256, tgsm>>>(A2, Wfc, fc1b, fc1b, 3, hcat, 768);

    // windowed attention -> second half of hcat
    attn_kernel<<<M_ / 8, 256>>>(hcat, attnW, wsp);

    // ---- layer 2 ----
    split_prep_kernel<<<(APQ + 255) / 256, 256>>>(hcat, A2, APQ, 0);
    split_prep_kernel<<<(WPQ + 255) / 256, 256>>>(l2Wihf, W2b, WPQ, 1);
    split_prep_kernel<<<(WPQ + 255) / 256, 256>>>(l2Wihb, W2b + (size_t)G4 * K2, WPQ, 1);
    tgemm_kernel<<<xp_grid, 256, tgsm>>>(A2, W2b, l2bf, l2bb, 12, xpAll, G8);
    flags_zero_kernel<<<1, 128>>>();
    lstm_scan_kernel<<<NCTA, TPB, lsm>>>(xpAll, l2Whhf, l2Whhb, lstm);

    // fc1 again (tensor) -> h2 (ldc=384)
    split_prep_kernel<<<(APQ + 255) / 256, 256>>>(lstm, A2, APQ, 0);
    tgemm_kernel<<<fc_grid, 256, tgsm>>>(A2, Wfc, fc1b, fc1b, 3, h2, H_);

    // MLP head
    gemm_bias_kernel<1><<<dim3(2, M_ / 128), 256>>>(h2,   W1, b1, mlp1, M_, 256, H_,  256);
    gemm_bias_kernel<1><<<dim3(1, M_ / 128), 256>>>(mlp1, W2, b2, mlp2, M_, 96,  256, 96);
    gemv_kernel<<<M_ / 8, 256>>>(mlp2, W3, b3, (float*)d_out);
}